// round 12
// baseline (speedup 1.0000x reference)
#include <cuda_runtime.h>
#include <cuda_fp16.h>
#include <cstdint>

// IntraAgg: segment-mean neighbor aggregation, fp16-table path.
// K1 (fused): f32->fp16 table (16 floats/thread) + segment bounds.
// K2: ONE WARP PER SEGMENT PER CTA (perfect retirement balance), barrier-free
//     per-thread cp.async ring, 4-row commit groups, 4-row HADD2 tree.
//   d_in[0] features    float32 [100000*256]
//   d_in[1] neigh_idx   int32   [524288]
//   d_in[2] segment_ids int32   [524288] (sorted ascending)
//   d_in[3] self_feats  float32 [16384*256]
// output: float32 [16384*512] = concat(self - agg, agg)

#define D_FEAT   256
#define N_BATCH  16384
#define N_NODES  100000
#define STAGES   16               // ring: 16 rows = 4 groups of 4 (8KB smem)
#define ROW_B    (D_FEAT * 2)     // 512 bytes per fp16 row

__device__ int g_seg_start[N_BATCH + 1];
__device__ __align__(16) __half g_feat_h[(size_t)N_NODES * D_FEAT];  // 51.2 MB scratch

// Fused prep: 16 floats per thread f32->fp16 + segment-boundary detection.
// (16 floats/thread measured best; 32 regressed — do not widen.)
__global__ void prep_kernel(const float* __restrict__ f, int n16,
                            const int* __restrict__ seg_ids, int n_edges)
{
    const int i = blockIdx.x * blockDim.x + threadIdx.x;

    if (i < n16) {
        const float4* s = reinterpret_cast<const float4*>(f) + 4 * (size_t)i;
        const float4 a = __ldcs(s);
        const float4 c = __ldcs(s + 1);
        const float4 d = __ldcs(s + 2);
        const float4 e = __ldcs(s + 3);
        __half2 h[8];
        h[0] = __floats2half2_rn(a.x, a.y);  h[1] = __floats2half2_rn(a.z, a.w);
        h[2] = __floats2half2_rn(c.x, c.y);  h[3] = __floats2half2_rn(c.z, c.w);
        h[4] = __floats2half2_rn(d.x, d.y);  h[5] = __floats2half2_rn(d.z, d.w);
        h[6] = __floats2half2_rn(e.x, e.y);  h[7] = __floats2half2_rn(e.z, e.w);
        uint4* dst = reinterpret_cast<uint4*>(g_feat_h + 16 * (size_t)i);
        dst[0] = reinterpret_cast<const uint4*>(h)[0];
        dst[1] = reinterpret_cast<const uint4*>(h)[1];
    }

    if (i < n_edges) {
        const int s_cur  = __ldg(seg_ids + i);
        const int s_prev = (i == 0) ? -1 : __ldg(seg_ids + i - 1);
        for (int b = s_prev + 1; b <= s_cur; ++b)
            g_seg_start[b] = i;
        if (i == n_edges - 1)
            for (int b = s_cur + 1; b <= N_BATCH; ++b)
                g_seg_start[b] = n_edges;
    }
}

__device__ __forceinline__ uint32_t smem_u32(const void* p)
{
    return (uint32_t)__cvta_generic_to_shared(p);
}

__device__ __forceinline__ void cp16(uint32_t dst, const void* src)
{
    asm volatile("cp.async.cg.shared.global [%0], [%1], 16;"
                 :: "r"(dst), "l"(src) : "memory");
}

__device__ __forceinline__ void cp_commit()
{
    asm volatile("cp.async.commit_group;" ::: "memory");
}

__global__ __launch_bounds__(32) void intra_agg_kernel(
    const int* __restrict__ neigh_idx,
    const float* __restrict__ self_feats,
    float* __restrict__ out)
{
    // One warp per CTA per segment: CTAs retire independently (no imbalance
    // hold). Lane owns bytes [16*lane,16*lane+16) of each 512B fp16 row; no
    // cross-thread smem sharing -> no barriers anywhere.
    __shared__ __align__(16) float4 buf[STAGES][32];

    const int lane = threadIdx.x;
    const int b    = blockIdx.x;

    const int start = g_seg_start[b];
    const int cnt   = g_seg_start[b + 1] - start;
    const int ngroups = (cnt + 3) >> 2;          // 4 rows per commit group

    const char* fbase = reinterpret_cast<const char*>(g_feat_h);
    const size_t col = (size_t)lane * 16;
    const int* eidx = neigh_idx + start;

    // ---- prologue: up to 4 groups of 4 rows
    #pragma unroll
    for (int gj = 0; gj < 4; ++gj) {
        if (gj < ngroups) {
            const int r0 = 4 * gj;
            #pragma unroll
            for (int j = 0; j < 4; ++j) {
                if (r0 + j < cnt) {
                    const int n = __ldg(eidx + r0 + j);
                    cp16(smem_u32(&buf[r0 + j][lane]), fbase + (size_t)n * ROW_B + col);
                }
            }
            cp_commit();
        }
    }

    float2 acc0 = make_float2(0.f, 0.f);
    float2 acc1 = make_float2(0.f, 0.f);
    float2 acc2 = make_float2(0.f, 0.f);
    float2 acc3 = make_float2(0.f, 0.f);

    auto cvt_add = [&](__half2 s0, __half2 s1, __half2 s2, __half2 s3) {
        float2 p;
        p = __half22float2(s0); acc0.x += p.x; acc0.y += p.y;
        p = __half22float2(s1); acc1.x += p.x; acc1.y += p.y;
        p = __half22float2(s2); acc2.x += p.x; acc2.y += p.y;
        p = __half22float2(s3); acc3.x += p.x; acc3.y += p.y;
    };
    // 4-row tree: 3 levels of HADD2, one cvt+add per 4 rows
    auto accum4 = [&](float4 A, float4 B, float4 C, float4 D) {
        const __half2* a = reinterpret_cast<const __half2*>(&A);
        const __half2* bq = reinterpret_cast<const __half2*>(&B);
        const __half2* c = reinterpret_cast<const __half2*>(&C);
        const __half2* d = reinterpret_cast<const __half2*>(&D);
        cvt_add(__hadd2(__hadd2(a[0], bq[0]), __hadd2(c[0], d[0])),
                __hadd2(__hadd2(a[1], bq[1]), __hadd2(c[1], d[1])),
                __hadd2(__hadd2(a[2], bq[2]), __hadd2(c[2], d[2])),
                __hadd2(__hadd2(a[3], bq[3]), __hadd2(c[3], d[3])));
    };
    auto accum2 = [&](float4 A, float4 B) {
        const __half2* a = reinterpret_cast<const __half2*>(&A);
        const __half2* bq = reinterpret_cast<const __half2*>(&B);
        cvt_add(__hadd2(a[0], bq[0]), __hadd2(a[1], bq[1]),
                __hadd2(a[2], bq[2]), __hadd2(a[3], bq[3]));
    };
    auto accum1 = [&](float4 A) {
        const __half2* a = reinterpret_cast<const __half2*>(&A);
        cvt_add(a[0], a[1], a[2], a[3]);
    };

    // ---- steady state: group g guaranteed full (4 rows); refill group g+4.
    int g = 0;
    #pragma unroll 1
    for (; g + 4 < ngroups; ++g) {
        const int rr = 4 * (g + 4);
        const int n0 = __ldg(eidx + rr);
        const int n1 = (rr + 1 < cnt) ? __ldg(eidx + rr + 1) : n0;
        const int n2 = (rr + 2 < cnt) ? __ldg(eidx + rr + 2) : n0;
        const int n3 = (rr + 3 < cnt) ? __ldg(eidx + rr + 3) : n0;

        asm volatile("cp.async.wait_group 3;" ::: "memory");
        const int s0 = (4 * g) & (STAGES - 1);
        const float4 f0 = buf[s0][lane];
        const float4 f1 = buf[s0 + 1][lane];
        const float4 f2 = buf[s0 + 2][lane];
        const float4 f3 = buf[s0 + 3][lane];

        cp16(smem_u32(&buf[s0][lane]),     fbase + (size_t)n0 * ROW_B + col);
        if (rr + 1 < cnt) cp16(smem_u32(&buf[s0 + 1][lane]), fbase + (size_t)n1 * ROW_B + col);
        if (rr + 2 < cnt) cp16(smem_u32(&buf[s0 + 2][lane]), fbase + (size_t)n2 * ROW_B + col);
        if (rr + 3 < cnt) cp16(smem_u32(&buf[s0 + 3][lane]), fbase + (size_t)n3 * ROW_B + col);
        cp_commit();

        accum4(f0, f1, f2, f3);
    }

    // ---- tail: drain, consume rows [4g, cnt)
    asm volatile("cp.async.wait_group 0;" ::: "memory");
    int r = 4 * g;
    #pragma unroll 1
    for (; r + 3 < cnt; r += 4)
        accum4(buf[r & (STAGES - 1)][lane],       buf[(r + 1) & (STAGES - 1)][lane],
               buf[(r + 2) & (STAGES - 1)][lane], buf[(r + 3) & (STAGES - 1)][lane]);
    if (r + 1 < cnt) {
        accum2(buf[r & (STAGES - 1)][lane], buf[(r + 1) & (STAGES - 1)][lane]);
        r += 2;
    }
    if (r < cnt)
        accum1(buf[r & (STAGES - 1)][lane]);

    const float inv = 1.0f / fmaxf((float)cnt, 1.0f);
    const float4 agg0 = make_float4(acc0.x * inv, acc0.y * inv, acc1.x * inv, acc1.y * inv);
    const float4 agg1 = make_float4(acc2.x * inv, acc2.y * inv, acc3.x * inv, acc3.y * inv);

    const float4* sp = reinterpret_cast<const float4*>(self_feats + (size_t)b * D_FEAT) + 2 * lane;
    const float4 s0 = __ldcs(sp);
    const float4 s1 = __ldcs(sp + 1);
    const float4 d0 = make_float4(s0.x - agg0.x, s0.y - agg0.y, s0.z - agg0.z, s0.w - agg0.w);
    const float4 d1 = make_float4(s1.x - agg1.x, s1.y - agg1.y, s1.z - agg1.z, s1.w - agg1.w);

    float* orow = out + (size_t)b * (2 * D_FEAT);
    __stcs(reinterpret_cast<float4*>(orow) + 2 * lane, d0);
    __stcs(reinterpret_cast<float4*>(orow) + 2 * lane + 1, d1);
    __stcs(reinterpret_cast<float4*>(orow + D_FEAT) + 2 * lane, agg0);
    __stcs(reinterpret_cast<float4*>(orow + D_FEAT) + 2 * lane + 1, agg1);
}

extern "C" void kernel_launch(void* const* d_in, const int* in_sizes, int n_in,
                              void* d_out, int out_size)
{
    const float* features   = (const float*)d_in[0];
    const int*   neigh_idx  = (const int*)d_in[1];
    const int*   seg_ids    = (const int*)d_in[2];
    const float* self_feats = (const float*)d_in[3];
    float*       out        = (float*)d_out;

    const int n_edges = in_sizes[1];
    const int n_batch = in_sizes[3] / D_FEAT;   // 16384
    const int n16 = in_sizes[0] / 16;           // 16 floats per prep thread

    const int prep_threads = (n16 > n_edges) ? n16 : n_edges;
    prep_kernel<<<(prep_threads + 255) / 256, 256>>>(features, n16, seg_ids, n_edges);
    intra_agg_kernel<<<n_batch, 32>>>(neigh_idx, self_feats, out);
}

// round 13
// speedup vs baseline: 1.2212x; 1.2212x over previous
#include <cuda_runtime.h>
#include <cuda_fp16.h>
#include <cstdint>

// IntraAgg: segment-mean neighbor aggregation, fp16-table path.
// K1 (fused): f32->fp16 table (16 floats/thread, measured-best) + segment
//             bounds + work-counter reset.
// K2: dynamic warp scheduling (atomic segment counter) -> no straggler hold;
//     2 warps/CTA for occupancy; per-warp barrier-free cp.async ring with
//     4-row commit groups and a 4-row HADD2 reduction tree.
//   d_in[0] features    float32 [100000*256]
//   d_in[1] neigh_idx   int32   [524288]
//   d_in[2] segment_ids int32   [524288] (sorted ascending)
//   d_in[3] self_feats  float32 [16384*256]
// output: float32 [16384*512] = concat(self - agg, agg)

#define D_FEAT   256
#define N_BATCH  16384
#define N_NODES  100000
#define ROW_B    (D_FEAT * 2)     // 512 bytes per fp16 row
#define STAGES   8                // per-warp ring: 2 groups of 4 rows (4KB)
#define TPB      64
#define GRID_G   4096             // ~28 CTAs/SM resident, single wave

__device__ int g_seg_start[N_BATCH + 1];
__device__ int g_counter;
__device__ __align__(16) __half g_feat_h[(size_t)N_NODES * D_FEAT];  // 51.2 MB

// Fused prep: 16 floats/thread f32->fp16 + bounds + counter reset.
__global__ void prep_kernel(const float* __restrict__ f, int n16,
                            const int* __restrict__ seg_ids, int n_edges)
{
    const int i = blockIdx.x * blockDim.x + threadIdx.x;

    if (i == 0) g_counter = 0;

    if (i < n16) {
        const float4* s = reinterpret_cast<const float4*>(f) + 4 * (size_t)i;
        const float4 a = __ldcs(s);
        const float4 c = __ldcs(s + 1);
        const float4 d = __ldcs(s + 2);
        const float4 e = __ldcs(s + 3);
        __half2 h[8];
        h[0] = __floats2half2_rn(a.x, a.y);  h[1] = __floats2half2_rn(a.z, a.w);
        h[2] = __floats2half2_rn(c.x, c.y);  h[3] = __floats2half2_rn(c.z, c.w);
        h[4] = __floats2half2_rn(d.x, d.y);  h[5] = __floats2half2_rn(d.z, d.w);
        h[6] = __floats2half2_rn(e.x, e.y);  h[7] = __floats2half2_rn(e.z, e.w);
        uint4* dst = reinterpret_cast<uint4*>(g_feat_h + 16 * (size_t)i);
        dst[0] = reinterpret_cast<const uint4*>(h)[0];
        dst[1] = reinterpret_cast<const uint4*>(h)[1];
    }

    if (i < n_edges) {
        const int s_cur  = __ldg(seg_ids + i);
        const int s_prev = (i == 0) ? -1 : __ldg(seg_ids + i - 1);
        for (int b = s_prev + 1; b <= s_cur; ++b)
            g_seg_start[b] = i;
        if (i == n_edges - 1)
            for (int b = s_cur + 1; b <= N_BATCH; ++b)
                g_seg_start[b] = n_edges;
    }
}

__device__ __forceinline__ uint32_t smem_u32(const void* p)
{
    return (uint32_t)__cvta_generic_to_shared(p);
}

__device__ __forceinline__ void cp16(uint32_t dst, const void* src)
{
    asm volatile("cp.async.cg.shared.global [%0], [%1], 16;"
                 :: "r"(dst), "l"(src) : "memory");
}

__device__ __forceinline__ void cp_commit()
{
    asm volatile("cp.async.commit_group;" ::: "memory");
}

__global__ __launch_bounds__(TPB) void intra_agg_kernel(
    const int* __restrict__ neigh_idx,
    const float* __restrict__ self_feats,
    float* __restrict__ out)
{
    // warp-private ring: lane owns 16B of each 512B row; no cross-thread smem
    // sharing -> no barriers. Warps draw segments from a global counter.
    __shared__ __align__(16) float4 buf[2][STAGES][32];

    const int w    = threadIdx.x >> 5;
    const int lane = threadIdx.x & 31;
    const char* fbase = reinterpret_cast<const char*>(g_feat_h);
    const size_t col = (size_t)lane * 16;

    float2 acc0, acc1, acc2, acc3;

    auto cvt_add = [&](__half2 s0, __half2 s1, __half2 s2, __half2 s3) {
        float2 p;
        p = __half22float2(s0); acc0.x += p.x; acc0.y += p.y;
        p = __half22float2(s1); acc1.x += p.x; acc1.y += p.y;
        p = __half22float2(s2); acc2.x += p.x; acc2.y += p.y;
        p = __half22float2(s3); acc3.x += p.x; acc3.y += p.y;
    };
    auto accum4 = [&](float4 A, float4 B, float4 C, float4 D) {
        const __half2* a = reinterpret_cast<const __half2*>(&A);
        const __half2* bq = reinterpret_cast<const __half2*>(&B);
        const __half2* c = reinterpret_cast<const __half2*>(&C);
        const __half2* d = reinterpret_cast<const __half2*>(&D);
        cvt_add(__hadd2(__hadd2(a[0], bq[0]), __hadd2(c[0], d[0])),
                __hadd2(__hadd2(a[1], bq[1]), __hadd2(c[1], d[1])),
                __hadd2(__hadd2(a[2], bq[2]), __hadd2(c[2], d[2])),
                __hadd2(__hadd2(a[3], bq[3]), __hadd2(c[3], d[3])));
    };
    auto accum1 = [&](float4 A) {
        const __half2* a = reinterpret_cast<const __half2*>(&A);
        cvt_add(a[0], a[1], a[2], a[3]);
    };

    while (true) {
        int b;
        if (lane == 0) b = atomicAdd(&g_counter, 1);
        b = __shfl_sync(0xffffffffu, b, 0);
        if (b >= N_BATCH) break;

        const int start = g_seg_start[b];
        const int cnt   = g_seg_start[b + 1] - start;
        const int ngroups = (cnt + 3) >> 2;
        const int* eidx = neigh_idx + start;

        // prologue: issue up to 2 groups of 4 rows
        #pragma unroll
        for (int gj = 0; gj < 2; ++gj) {
            if (gj < ngroups) {
                const int r0 = 4 * gj;
                #pragma unroll
                for (int j = 0; j < 4; ++j) {
                    if (r0 + j < cnt) {
                        const int n = __ldg(eidx + r0 + j);
                        cp16(smem_u32(&buf[w][r0 + j][lane]),
                             fbase + (size_t)n * ROW_B + col);
                    }
                }
                cp_commit();
            }
        }

        acc0 = make_float2(0.f, 0.f);
        acc1 = make_float2(0.f, 0.f);
        acc2 = make_float2(0.f, 0.f);
        acc3 = make_float2(0.f, 0.f);

        // steady state: group g full; consume it, issue group g+2
        int g = 0;
        #pragma unroll 1
        for (; g + 2 < ngroups; ++g) {
            const int rr = 4 * (g + 2);
            const int n0 = __ldg(eidx + rr);
            const int n1 = (rr + 1 < cnt) ? __ldg(eidx + rr + 1) : n0;
            const int n2 = (rr + 2 < cnt) ? __ldg(eidx + rr + 2) : n0;
            const int n3 = (rr + 3 < cnt) ? __ldg(eidx + rr + 3) : n0;

            asm volatile("cp.async.wait_group 1;" ::: "memory");
            const int s0 = (4 * g) & (STAGES - 1);
            const float4 f0 = buf[w][s0][lane];
            const float4 f1 = buf[w][s0 + 1][lane];
            const float4 f2 = buf[w][s0 + 2][lane];
            const float4 f3 = buf[w][s0 + 3][lane];

            cp16(smem_u32(&buf[w][s0][lane]), fbase + (size_t)n0 * ROW_B + col);
            if (rr + 1 < cnt) cp16(smem_u32(&buf[w][s0 + 1][lane]), fbase + (size_t)n1 * ROW_B + col);
            if (rr + 2 < cnt) cp16(smem_u32(&buf[w][s0 + 2][lane]), fbase + (size_t)n2 * ROW_B + col);
            if (rr + 3 < cnt) cp16(smem_u32(&buf[w][s0 + 3][lane]), fbase + (size_t)n3 * ROW_B + col);
            cp_commit();

            accum4(f0, f1, f2, f3);
        }

        // drain + tail rows [4g, cnt)
        asm volatile("cp.async.wait_group 0;" ::: "memory");
        int r = 4 * g;
        #pragma unroll 1
        for (; r + 3 < cnt; r += 4)
            accum4(buf[w][r & (STAGES - 1)][lane],       buf[w][(r + 1) & (STAGES - 1)][lane],
                   buf[w][(r + 2) & (STAGES - 1)][lane], buf[w][(r + 3) & (STAGES - 1)][lane]);
        #pragma unroll 1
        for (; r < cnt; ++r)
            accum1(buf[w][r & (STAGES - 1)][lane]);

        const float inv = 1.0f / fmaxf((float)cnt, 1.0f);
        const float4 agg0 = make_float4(acc0.x * inv, acc0.y * inv, acc1.x * inv, acc1.y * inv);
        const float4 agg1 = make_float4(acc2.x * inv, acc2.y * inv, acc3.x * inv, acc3.y * inv);

        const float4* sp = reinterpret_cast<const float4*>(self_feats + (size_t)b * D_FEAT) + 2 * lane;
        const float4 s0 = __ldcs(sp);
        const float4 s1 = __ldcs(sp + 1);
        const float4 d0 = make_float4(s0.x - agg0.x, s0.y - agg0.y, s0.z - agg0.z, s0.w - agg0.w);
        const float4 d1 = make_float4(s1.x - agg1.x, s1.y - agg1.y, s1.z - agg1.z, s1.w - agg1.w);

        float* orow = out + (size_t)b * (2 * D_FEAT);
        __stcs(reinterpret_cast<float4*>(orow) + 2 * lane, d0);
        __stcs(reinterpret_cast<float4*>(orow) + 2 * lane + 1, d1);
        __stcs(reinterpret_cast<float4*>(orow + D_FEAT) + 2 * lane, agg0);
        __stcs(reinterpret_cast<float4*>(orow + D_FEAT) + 2 * lane + 1, agg1);
    }
}

extern "C" void kernel_launch(void* const* d_in, const int* in_sizes, int n_in,
                              void* d_out, int out_size)
{
    const float* features   = (const float*)d_in[0];
    const int*   neigh_idx  = (const int*)d_in[1];
    const int*   seg_ids    = (const int*)d_in[2];
    const float* self_feats = (const float*)d_in[3];
    float*       out        = (float*)d_out;

    const int n_edges = in_sizes[1];
    const int n16 = in_sizes[0] / 16;

    const int prep_threads = (n16 > n_edges) ? n16 : n_edges;
    prep_kernel<<<(prep_threads + 255) / 256, 256>>>(features, n16, seg_ids, n_edges);
    intra_agg_kernel<<<GRID_G, TPB>>>(neigh_idx, self_feats, out);
}

// round 14
// speedup vs baseline: 1.3683x; 1.1205x over previous
#include <cuda_runtime.h>
#include <cuda_fp16.h>
#include <cstdint>

// IntraAgg: segment-mean neighbor aggregation, fp16-table path.
// K1 (fused): f32->fp16 table (16 floats/thread, measured-best) + bounds.
// K2: warp-per-segment (4 warps/CTA for occupancy), barrier-free per-thread
//     cp.async ring, 4 commit groups x 2 rows, wait_group 3 (R11 mainloop),
//     pairwise HADD2 accumulation. __launch_bounds__(128,12) caps regs.
//   d_in[0] features    float32 [100000*256]
//   d_in[1] neigh_idx   int32   [524288]
//   d_in[2] segment_ids int32   [524288] (sorted ascending)
//   d_in[3] self_feats  float32 [16384*256]
// output: float32 [16384*512] = concat(self - agg, agg)

#define D_FEAT   256
#define N_BATCH  16384
#define N_NODES  100000
#define STAGES   8                // per-warp ring: 4 groups of 2 rows (4KB)
#define TPB      128              // 4 warps, each owns one segment
#define WPB      4
#define ROW_B    (D_FEAT * 2)     // 512 bytes per fp16 row

__device__ int g_seg_start[N_BATCH + 1];
__device__ __align__(16) __half g_feat_h[(size_t)N_NODES * D_FEAT];  // 51.2 MB

// Fused prep: 16 floats/thread f32->fp16 + segment bounds (measured-best).
__global__ void prep_kernel(const float* __restrict__ f, int n16,
                            const int* __restrict__ seg_ids, int n_edges)
{
    const int i = blockIdx.x * blockDim.x + threadIdx.x;

    if (i < n16) {
        const float4* s = reinterpret_cast<const float4*>(f) + 4 * (size_t)i;
        const float4 a = __ldcs(s);
        const float4 c = __ldcs(s + 1);
        const float4 d = __ldcs(s + 2);
        const float4 e = __ldcs(s + 3);
        __half2 h[8];
        h[0] = __floats2half2_rn(a.x, a.y);  h[1] = __floats2half2_rn(a.z, a.w);
        h[2] = __floats2half2_rn(c.x, c.y);  h[3] = __floats2half2_rn(c.z, c.w);
        h[4] = __floats2half2_rn(d.x, d.y);  h[5] = __floats2half2_rn(d.z, d.w);
        h[6] = __floats2half2_rn(e.x, e.y);  h[7] = __floats2half2_rn(e.z, e.w);
        uint4* dst = reinterpret_cast<uint4*>(g_feat_h + 16 * (size_t)i);
        dst[0] = reinterpret_cast<const uint4*>(h)[0];
        dst[1] = reinterpret_cast<const uint4*>(h)[1];
    }

    if (i < n_edges) {
        const int s_cur  = __ldg(seg_ids + i);
        const int s_prev = (i == 0) ? -1 : __ldg(seg_ids + i - 1);
        for (int b = s_prev + 1; b <= s_cur; ++b)
            g_seg_start[b] = i;
        if (i == n_edges - 1)
            for (int b = s_cur + 1; b <= N_BATCH; ++b)
                g_seg_start[b] = n_edges;
    }
}

__device__ __forceinline__ uint32_t smem_u32(const void* p)
{
    return (uint32_t)__cvta_generic_to_shared(p);
}

__device__ __forceinline__ void cp16(uint32_t dst, const void* src)
{
    asm volatile("cp.async.cg.shared.global [%0], [%1], 16;"
                 :: "r"(dst), "l"(src) : "memory");
}

__device__ __forceinline__ void cp_commit()
{
    asm volatile("cp.async.commit_group;" ::: "memory");
}

__global__ __launch_bounds__(TPB, 12) void intra_agg_kernel(
    const int* __restrict__ neigh_idx,
    const float* __restrict__ self_feats,
    float* __restrict__ out)
{
    // warp w owns segment blockIdx.x*WPB+w; lane owns 16B of each 512B row.
    // No cross-thread smem sharing -> no barriers anywhere.
    __shared__ __align__(16) float4 buf[WPB][STAGES][32];

    const int w    = threadIdx.x >> 5;
    const int lane = threadIdx.x & 31;
    const int b    = blockIdx.x * WPB + w;

    const int start = g_seg_start[b];
    const int cnt   = g_seg_start[b + 1] - start;
    const int ngroups = (cnt + 1) >> 1;          // 2 rows per commit group

    const char* fbase = reinterpret_cast<const char*>(g_feat_h);
    const size_t col = (size_t)lane * 16;
    const int* eidx = neigh_idx + start;

    // ---- prologue: up to 4 groups of 2 rows
    #pragma unroll
    for (int gj = 0; gj < 4; ++gj) {
        if (gj < ngroups) {
            const int r0 = 2 * gj;
            const int n0 = __ldg(eidx + r0);
            cp16(smem_u32(&buf[w][r0][lane]), fbase + (size_t)n0 * ROW_B + col);
            if (r0 + 1 < cnt) {
                const int n1 = __ldg(eidx + r0 + 1);
                cp16(smem_u32(&buf[w][r0 + 1][lane]), fbase + (size_t)n1 * ROW_B + col);
            }
            cp_commit();
        }
    }

    float2 acc0 = make_float2(0.f, 0.f);
    float2 acc1 = make_float2(0.f, 0.f);
    float2 acc2 = make_float2(0.f, 0.f);
    float2 acc3 = make_float2(0.f, 0.f);

    auto accum_pair = [&](float4 A, float4 B) {
        const __half2* ha = reinterpret_cast<const __half2*>(&A);
        const __half2* hb = reinterpret_cast<const __half2*>(&B);
        float2 p;
        p = __half22float2(__hadd2(ha[0], hb[0])); acc0.x += p.x; acc0.y += p.y;
        p = __half22float2(__hadd2(ha[1], hb[1])); acc1.x += p.x; acc1.y += p.y;
        p = __half22float2(__hadd2(ha[2], hb[2])); acc2.x += p.x; acc2.y += p.y;
        p = __half22float2(__hadd2(ha[3], hb[3])); acc3.x += p.x; acc3.y += p.y;
    };
    auto accum_one = [&](float4 A) {
        const __half2* ha = reinterpret_cast<const __half2*>(&A);
        float2 p;
        p = __half22float2(ha[0]); acc0.x += p.x; acc0.y += p.y;
        p = __half22float2(ha[1]); acc1.x += p.x; acc1.y += p.y;
        p = __half22float2(ha[2]); acc2.x += p.x; acc2.y += p.y;
        p = __half22float2(ha[3]); acc3.x += p.x; acc3.y += p.y;
    };

    // ---- steady state (R11 mainloop): wait_group 3, consume 2 rows pairwise,
    // refill with group g+4, indices prefetched one iteration ahead.
    int g = 0;
    int nx0 = 0, nx1 = 0;
    if (4 < ngroups) {
        nx0 = __ldg(eidx + 8);
        nx1 = (9 < cnt) ? __ldg(eidx + 9) : nx0;
    }
    #pragma unroll 1
    for (; g + 4 < ngroups; ++g) {
        asm volatile("cp.async.wait_group 3;" ::: "memory");
        const int s0 = (2 * g) & (STAGES - 1);
        const float4 f0 = buf[w][s0][lane];
        const float4 f1 = buf[w][s0 + 1][lane];

        const int rr = 2 * (g + 4);
        cp16(smem_u32(&buf[w][s0][lane]), fbase + (size_t)nx0 * ROW_B + col);
        if (rr + 1 < cnt)
            cp16(smem_u32(&buf[w][s0 + 1][lane]), fbase + (size_t)nx1 * ROW_B + col);
        cp_commit();

        if (g + 5 < ngroups) {
            const int rn = 2 * (g + 5);
            nx0 = __ldg(eidx + rn);
            nx1 = (rn + 1 < cnt) ? __ldg(eidx + rn + 1) : nx0;
        }

        accum_pair(f0, f1);
    }

    // ---- tail: drain, consume rows [2g, cnt)
    asm volatile("cp.async.wait_group 0;" ::: "memory");
    int r = 2 * g;
    #pragma unroll 1
    for (; r + 1 < cnt; r += 2)
        accum_pair(buf[w][r & (STAGES - 1)][lane],
                   buf[w][(r + 1) & (STAGES - 1)][lane]);
    if (r < cnt)
        accum_one(buf[w][r & (STAGES - 1)][lane]);

    const float inv = 1.0f / fmaxf((float)cnt, 1.0f);
    const float4 agg0 = make_float4(acc0.x * inv, acc0.y * inv, acc1.x * inv, acc1.y * inv);
    const float4 agg1 = make_float4(acc2.x * inv, acc2.y * inv, acc3.x * inv, acc3.y * inv);

    const float4* sp = reinterpret_cast<const float4*>(self_feats + (size_t)b * D_FEAT) + 2 * lane;
    const float4 s0 = __ldcs(sp);
    const float4 s1 = __ldcs(sp + 1);
    const float4 d0 = make_float4(s0.x - agg0.x, s0.y - agg0.y, s0.z - agg0.z, s0.w - agg0.w);
    const float4 d1 = make_float4(s1.x - agg1.x, s1.y - agg1.y, s1.z - agg1.z, s1.w - agg1.w);

    float* orow = out + (size_t)b * (2 * D_FEAT);
    __stcs(reinterpret_cast<float4*>(orow) + 2 * lane, d0);
    __stcs(reinterpret_cast<float4*>(orow) + 2 * lane + 1, d1);
    __stcs(reinterpret_cast<float4*>(orow + D_FEAT) + 2 * lane, agg0);
    __stcs(reinterpret_cast<float4*>(orow + D_FEAT) + 2 * lane + 1, agg1);
}

extern "C" void kernel_launch(void* const* d_in, const int* in_sizes, int n_in,
                              void* d_out, int out_size)
{
    const float* features   = (const float*)d_in[0];
    const int*   neigh_idx  = (const int*)d_in[1];
    const int*   seg_ids    = (const int*)d_in[2];
    const float* self_feats = (const float*)d_in[3];
    float*       out        = (float*)d_out;

    const int n_edges = in_sizes[1];
    const int n_batch = in_sizes[3] / D_FEAT;   // 16384
    const int n16 = in_sizes[0] / 16;

    const int prep_threads = (n16 > n_edges) ? n16 : n_edges;
    prep_kernel<<<(prep_threads + 255) / 256, 256>>>(features, n16, seg_ids, n_edges);
    intra_agg_kernel<<<n_batch / WPB, TPB>>>(neigh_idx, self_feats, out);
}